// round 16
// baseline (speedup 1.0000x reference)
#include <cuda_runtime.h>
#include <cuda_fp16.h>
#include <cstdint>

// Problem constants
#define TOK   65536      // B*L
#define BATCH 64
#define SEQL  1024
#define HID   512
#define FF    1024
#define HALF_ 256
#define VOC   32000

typedef __half half_t;

__device__ __forceinline__ uint32_t smem_u32(const void* p) {
    uint32_t a;
    asm("{ .reg .u64 t; cvta.to.shared.u64 t, %1; cvt.u32.u64 %0, t; }" : "=r"(a) : "l"(p));
    return a;
}
#define SW128(o) ((o) ^ (((o) >> 3) & 0x70))

__device__ __forceinline__ void ldsm4(uint32_t* r, uint32_t a) {
    asm volatile("ldmatrix.sync.aligned.m8n8.x4.shared.b16 {%0,%1,%2,%3}, [%4];"
        : "=r"(r[0]), "=r"(r[1]), "=r"(r[2]), "=r"(r[3]) : "r"(a));
}
__device__ __forceinline__ void mma16816(float* c, const uint32_t* a, const uint32_t* b) {
    asm volatile("mma.sync.aligned.m16n8k16.row.col.f32.f16.f16.f32 "
        "{%0,%1,%2,%3}, {%4,%5,%6,%7}, {%8,%9}, {%0,%1,%2,%3};"
        : "+f"(c[0]), "+f"(c[1]), "+f"(c[2]), "+f"(c[3])
        : "r"(a[0]), "r"(a[1]), "r"(a[2]), "r"(a[3]), "r"(b[0]), "r"(b[1]));
}
__device__ __forceinline__ void cp16(uint32_t dst, const void* src, bool pred) {
    const int sz = pred ? 16 : 0;
    asm volatile("cp.async.cg.shared.global [%0], [%1], 16, %2;"
        :: "r"(dst), "l"(src), "r"(sz) : "memory");
}
#define CP_COMMIT() asm volatile("cp.async.commit_group;" ::: "memory")
template<int N>
__device__ __forceinline__ void cp_wait() {
    asm volatile("cp.async.wait_group %0;" :: "n"(N) : "memory");
}

// -------- scratch (device globals) --------
__device__ half_t g_ah[(size_t)TOK * HID];
__device__ half_t g_h1h[(size_t)TOK * FF];
__device__ half_t g_hh[(size_t)TOK * HID];
__device__ float  g_x[(size_t)TOK * HID];
__device__ float  g_k[(size_t)TOK * HID];
__device__ half_t g_w1h[(size_t)FF * HID];
__device__ half_t g_w2h[(size_t)HID * FF];
__device__ half_t g_wph[(size_t)HID * HID];
__device__ half_t g_owh[(size_t)VOC * HID];
__device__ float  g_bproj[HID];
__device__ half_t g_ch[BATCH * HID];

// ============================================================
// mma.sync fp16 single-pass GEMM, cp.async 3-stage pipeline, BK=64.
// C[M,N] = A[M,K] @ B^T;  A [M,K] K-major fp16, B [N,K] K-major fp16.
// 128x128 CTA tile, 256 threads (8 warps, 32x64 warp tile).
// smem layout: one 128B row = 64 contiguous fp16 k-elems (A and B alike),
// SW128 swizzle. Stage = 16KB A + 16KB B = 32KB; 3 stages; one sync/chunk.
// EPI: 0 = relu(acc+bias) -> fp16; 1 = acc+bias+embed[seq[m]] -> f32;
//      2 = acc+bias -> f32.
// ============================================================
#define GSTAGE 32768
#define NSTAGE 3
#define GSMEM  (NSTAGE * GSTAGE)

template<int EPI>
__global__ void __launch_bounds__(256, 2) mma_gemm(
    int Mrows, int N, int K,
    const half_t* __restrict__ Ah, const half_t* __restrict__ Bh,
    const float* __restrict__ bias,
    float* __restrict__ Cf, half_t* __restrict__ Chi,
    const int* __restrict__ seq, const float* __restrict__ embed)
{
    extern __shared__ __align__(1024) char smem[];
    const uint32_t sbase = smem_u32(smem);
    const int tid = threadIdx.x;
    const int bm = blockIdx.y * 128;
    const int bn = blockIdx.x * 128;
    const int wid = tid >> 5, lane = tid & 31;
    const int wm = (wid & 3) * 32;      // warp row offset (0..96)
    const int wn = (wid >> 2) * 64;     // warp col offset (0 / 64)
    const bool mguard = (Mrows & 127) != 0;

    // loader mapping: 2 threads per 128B row, 4x16B words each
    const int lrow = tid >> 1;
    const int lw4 = (tid & 1) * 4;
    const int am = bm + lrow;
    const bool av = !mguard || (am < Mrows);
    const size_t aoff = (size_t)(av ? am : 0) * K;
    const size_t boff = (size_t)(bn + lrow) * K;

    // A ldmatrix lane addressing (m16 x k16 per x4)
    const int a_mi = lane >> 3;
    const int a_row = (lane & 7) + (a_mi & 1) * 8;
    const int a_kb = (a_mi >> 1) * 16;
    // B ldmatrix lane addressing (2 n8 tiles x 2 k8-halves per x4)
    const int b_g = lane >> 3;
    const int b_row = lane & 7;
    const int b_nt = b_g >> 1;
    const int b_kh = (b_g & 1) * 16;

    float c[16][4];                     // [mt*8 + nt][4], mt<2, nt<8
#pragma unroll
    for (int i = 0; i < 16; i++)
#pragma unroll
        for (int j = 0; j < 4; j++) c[i][j] = 0.f;

    const int NCH = K >> 6;             // BK = 64

    auto load_stage = [&](int s, int k0) {
        const uint32_t sA = sbase + s * GSTAGE;
        const uint32_t sB = sA + 16384;
#pragma unroll
        for (int it = 0; it < 4; it++) {
            const int word = lw4 + it;             // 0..7
            const uint32_t so = SW128((uint32_t)(lrow * 128 + word * 16));
            const size_t ko = (size_t)(k0 + word * 8);
            cp16(sA + so, Ah + aoff + ko, av);
            cp16(sB + so, Bh + boff + ko, true);
        }
    };

    load_stage(0, 0);
    CP_COMMIT();
    load_stage(1, 64);
    CP_COMMIT();

    int stage = 0;
    for (int ch = 0; ch < NCH; ch++) {
        if (ch + 1 < NCH) cp_wait<1>(); else cp_wait<0>();
        __syncthreads();
        if (ch + 2 < NCH) {
            int ns = stage + 2; if (ns >= NSTAGE) ns -= NSTAGE;
            load_stage(ns, (ch + 2) * 64);
        }
        CP_COMMIT();   // always commit (possibly empty) to keep accounting
        const uint32_t sAu = sbase + stage * GSTAGE;
        const uint32_t sBu = sAu + 16384;
        // ---- compute: 4 k16 steps ----
#pragma unroll
        for (int k16 = 0; k16 < 4; k16++) {
            const int kb = k16 * 32;
            uint32_t bfrag[4][4];       // 8 n8 tiles (64 cols)
#pragma unroll
            for (int p = 0; p < 4; p++) {
                const int n = wn + (p * 2 + b_nt) * 8 + b_row;
                ldsm4(bfrag[p], sBu + SW128((uint32_t)(n * 128) + kb + b_kh));
            }
            uint32_t a[2][4];
#pragma unroll
            for (int mt = 0; mt < 2; mt++)
                ldsm4(a[mt], sAu + SW128((uint32_t)((wm + mt * 16 + a_row) * 128) + kb + a_kb));
#pragma unroll
            for (int mt = 0; mt < 2; mt++)
#pragma unroll
                for (int nt = 0; nt < 8; nt++)
                    mma16816(c[mt * 8 + nt], a[mt], &bfrag[nt >> 1][(nt & 1) * 2]);
        }
        if (++stage >= NSTAGE) stage = 0;
    }

    // ---- epilogue ----
    const int mrow = lane >> 2;
    const int mcol = (lane & 3) * 2;
#pragma unroll
    for (int mt = 0; mt < 2; mt++) {
        const int r0 = bm + wm + mt * 16 + mrow;
        const int r1 = r0 + 8;
        const bool v0 = !mguard || (r0 < Mrows);
        const bool v1 = !mguard || (r1 < Mrows);
        const float* e0 = nullptr;
        const float* e1 = nullptr;
        if (EPI == 1) {
            if (v0) e0 = embed + (size_t)seq[r0] * HID;
            if (v1) e1 = embed + (size_t)seq[r1] * HID;
        }
#pragma unroll
        for (int nt = 0; nt < 8; nt++) {
            const int col = bn + wn + nt * 8 + mcol;
            float* cc = c[mt * 8 + nt];
            const float b0v = bias[col], b1v = bias[col + 1];
            float x0 = cc[0] + b0v, x1 = cc[1] + b1v;
            float x2 = cc[2] + b0v, x3 = cc[3] + b1v;
            if (EPI == 0) {
                x0 = fmaxf(x0, 0.f); x1 = fmaxf(x1, 0.f);
                x2 = fmaxf(x2, 0.f); x3 = fmaxf(x3, 0.f);
                if (v0) {
                    __half2 ph; ph.x = __float2half_rn(x0); ph.y = __float2half_rn(x1);
                    *(__half2*)(Chi + (size_t)r0 * N + col) = ph;
                }
                if (v1) {
                    __half2 ph; ph.x = __float2half_rn(x2); ph.y = __float2half_rn(x3);
                    *(__half2*)(Chi + (size_t)r1 * N + col) = ph;
                }
            } else {
                if (EPI == 1) {
                    if (v0) { x0 += e0[col]; x1 += e0[col + 1]; }
                    if (v1) { x2 += e1[col]; x3 += e1[col + 1]; }
                }
                if (v0) *(float2*)(Cf + (size_t)r0 * N + col) = make_float2(x0, x1);
                if (v1) *(float2*)(Cf + (size_t)r1 * N + col) = make_float2(x2, x3);
            }
        }
    }
}

// ============================================================
// gather + round:  Ahi[m] = fp16(embed[seq[m]])
// ============================================================
__global__ void __launch_bounds__(256) gsplit_k(const int* __restrict__ seq,
                                                const float* __restrict__ embed,
                                                half_t* __restrict__ hi)
{
    const size_t idx = (size_t)blockIdx.x * 256 + threadIdx.x;   // TOK*64
    const int t = (int)(idx >> 6), c = (int)(idx & 63) * 8;
    const float* p = embed + (size_t)seq[t] * HID + c;
    float4 a = *(const float4*)p;
    float4 b = *(const float4*)(p + 4);
    float vv[8] = {a.x, a.y, a.z, a.w, b.x, b.y, b.z, b.w};
    const size_t ob = (size_t)t * HID + c;
#pragma unroll
    for (int j = 0; j < 8; j += 2) {
        __half2 ph; ph.x = __float2half_rn(vv[j]); ph.y = __float2half_rn(vv[j + 1]);
        *(__half2*)(hi + ob + j) = ph;
    }
}

// ============================================================
// Tiled transpose + round: W[K,N] fp32 -> out[N,K] single fp16.
// ============================================================
__global__ void __launch_bounds__(256) tsplit1_k(const float* __restrict__ W, int K, int N,
                                                 half_t* __restrict__ ht)
{
    __shared__ float t[32][33];
    const int tx = threadIdx.x & 31, ty = threadIdx.x >> 5;
    const int n0 = blockIdx.x * 32, k0 = blockIdx.y * 32;
#pragma unroll
    for (int i = 0; i < 4; i++)
        t[ty + 8 * i][tx] = W[(size_t)(k0 + ty + 8 * i) * N + n0 + tx];
    __syncthreads();
#pragma unroll
    for (int i = 0; i < 4; i++) {
        const size_t o = (size_t)(n0 + ty + 8 * i) * K + k0 + tx;
        ht[o] = __float2half_rn(t[tx][ty + 8 * i]);
    }
}

// ============================================================
// LayerNorm (warp per row) -> fp16 output.
// ============================================================
__global__ void __launch_bounds__(256) ln_split_k(const float* __restrict__ x,
                                                  const float* __restrict__ g,
                                                  const float* __restrict__ b,
                                                  half_t* __restrict__ hh)
{
    const int row = blockIdx.x * 8 + (threadIdx.x >> 5);
    const int ln = threadIdx.x & 31;
    const float* xr = x + (size_t)row * HID + ln * 16;
    float v[16];
    *(float4*)&v[0]  = ((const float4*)xr)[0];
    *(float4*)&v[4]  = ((const float4*)xr)[1];
    *(float4*)&v[8]  = ((const float4*)xr)[2];
    *(float4*)&v[12] = ((const float4*)xr)[3];
    float s = 0.f;
#pragma unroll
    for (int j = 0; j < 16; j++) s += v[j];
#pragma unroll
    for (int o = 16; o; o >>= 1) s += __shfl_xor_sync(0xffffffffu, s, o);
    const float mean = s * (1.f / 512.f);
    float q = 0.f;
#pragma unroll
    for (int j = 0; j < 16; j++) { float d = v[j] - mean; q += d * d; }
#pragma unroll
    for (int o = 16; o; o >>= 1) q += __shfl_xor_sync(0xffffffffu, q, o);
    const float r = rsqrtf(q * (1.f / 512.f) + 1e-5f);
    const size_t ob = (size_t)row * HID + ln * 16;
#pragma unroll
    for (int j = 0; j < 16; j += 2) {
        const int c0 = ln * 16 + j;
        float y0 = (v[j] - mean) * r * g[c0] + b[c0];
        float y1 = (v[j + 1] - mean) * r * g[c0 + 1] + b[c0 + 1];
        __half2 ph; ph.x = __float2half_rn(y0); ph.y = __float2half_rn(y1);
        *(__half2*)(hh + ob + j) = ph;
    }
}

// ============================================================
__global__ void bpack_k(const float* __restrict__ sb, const float* __restrict__ eb)
{
    const int i = blockIdx.x * 256 + threadIdx.x;
    if (i < HID) g_bproj[i] = (i < HALF_) ? sb[i] : eb[i - HALF_];
}

// ============================================================
// Backward vector scan, 2 steps per iteration, inline norms,
// depth-2 row prefetch, fp16 output (c for GEMM4).
// ============================================================
__global__ void __launch_bounds__(32) scan_k(const float* __restrict__ kall,
                                             half_t* __restrict__ chh)
{
    const int chain = blockIdx.x;
    const int b = chain >> 1, wh = chain & 1;
    const int ln = threadIdx.x;
    const float* base = kall + (size_t)b * SEQL * HID + wh * HALF_ + ln * 8;

#define LOADROW(dst, t) do { \
    float4 _a = *(const float4*)(base + (size_t)(t) * HID); \
    float4 _b = *(const float4*)(base + (size_t)(t) * HID + 4); \
    dst[0]=_a.x; dst[1]=_a.y; dst[2]=_a.z; dst[3]=_a.w; \
    dst[4]=_b.x; dst[5]=_b.y; dst[6]=_b.z; dst[7]=_b.w; } while (0)

    float u[8], acc[8], k0[8], k1[8], p0[8], p1[8];
    LOADROW(u, SEQL - 1);
#pragma unroll
    for (int j = 0; j < 8; j++) acc[j] = 0.f;

    // ---- single first step t = 1022 ----
    {
        float kc[8];
        LOADROW(kc, SEQL - 2);
        LOADROW(k0, SEQL - 3);   // t=1021
        LOADROW(k1, SEQL - 4);   // t=1020
        LOADROW(p0, SEQL - 5);   // t=1019
        LOADROW(p1, SEQL - 6);   // t=1018
        float pa = 0.f, n0 = 0.f;
#pragma unroll
        for (int j = 0; j < 8; j++) { pa += kc[j] * u[j]; n0 += kc[j] * kc[j]; }
#pragma unroll
        for (int o = 16; o; o >>= 1) {
            pa += __shfl_xor_sync(0xffffffffu, pa, o);
            n0 += __shfl_xor_sync(0xffffffffu, n0, o);
        }
        const float w = wh ? (1023.f / 1024.f) : 1.f;
        const float ws = w * pa;
        const float us = ws / (n0 + 1e-6f);
#pragma unroll
        for (int j = 0; j < 8; j++) { acc[j] += ws * kc[j]; u[j] -= us * kc[j]; }
    }

    // ---- pair loop: t = 1021, 1019, ..., 1 (511 iterations) ----
    for (int t = SEQL - 3; t >= 1; t -= 2) {
        float q0[8] = {0, 0, 0, 0, 0, 0, 0, 0};
        float q1[8] = {0, 0, 0, 0, 0, 0, 0, 0};
        if (t >= 5) {
            LOADROW(q0, t - 4);
            LOADROW(q1, t - 5);
        }
        float pa = 0.f, pb = 0.f, pg = 0.f, n0 = 0.f, n1 = 0.f;
#pragma unroll
        for (int j = 0; j < 8; j++) {
            pa += k0[j] * u[j];
            pb += k1[j] * u[j];
            pg += k1[j] * k0[j];
            n0 += k0[j] * k0[j];
            n1 += k1[j] * k1[j];
        }
#pragma unroll
        for (int o = 16; o; o >>= 1) {
            pa += __shfl_xor_sync(0xffffffffu, pa, o);
            pb += __shfl_xor_sync(0xffffffffu, pb, o);
            pg += __shfl_xor_sync(0xffffffffu, pg, o);
            n0 += __shfl_xor_sync(0xffffffffu, n0, o);
            n1 += __shfl_xor_sync(0xffffffffu, n1, o);
        }
        const float inv1024 = 1.f / 1024.f;
        const float w0 = wh ? (float)(t + 1) * inv1024 : 1.f;
        const float w1 = wh ? (float)t * inv1024 : 1.f;
        const float id0 = 1.f / (n0 + 1e-6f);
        const float id1 = 1.f / (n1 + 1e-6f);
        const float ws0 = w0 * pa;
        const float us0 = ws0 * id0;
        const float s1 = pb - us0 * pg;
        const float ws1 = w1 * s1;
        const float us1 = ws1 * id1;
#pragma unroll
        for (int j = 0; j < 8; j++) {
            acc[j] += ws0 * k0[j] + ws1 * k1[j];
            u[j]   -= us0 * k0[j] + us1 * k1[j];
        }
#pragma unroll
        for (int j = 0; j < 8; j++) {
            k0[j] = p0[j]; k1[j] = p1[j];
            p0[j] = q0[j]; p1[j] = q1[j];
        }
    }

    const size_t ob = (size_t)b * HID + wh * HALF_ + ln * 8;
#pragma unroll
    for (int j = 0; j < 8; j += 2) {
        __half2 ph;
        ph.x = __float2half_rn(acc[j]);
        ph.y = __float2half_rn(acc[j + 1]);
        *(__half2*)(chh + ob + j) = ph;
    }
#undef LOADROW
}

// ============================================================
extern "C" void kernel_launch(void* const* d_in, const int* in_sizes, int n_in,
                              void* d_out, int out_size)
{
    const int*   seq   = (const int*)d_in[0];
    const float* embed = (const float*)d_in[1];
    const float* w1    = (const float*)d_in[2];
    const float* b1    = (const float*)d_in[3];
    const float* w2    = (const float*)d_in[4];
    const float* b2    = (const float*)d_in[5];
    const float* lng   = (const float*)d_in[6];
    const float* lnb   = (const float*)d_in[7];
    const float* sw    = (const float*)d_in[8];
    const float* sb    = (const float*)d_in[9];
    const float* ew    = (const float*)d_in[10];
    const float* eb    = (const float*)d_in[11];
    const float* ow    = (const float*)d_in[12];
    const float* ob    = (const float*)d_in[13];
    float* out = (float*)d_out;

    static bool init = false;
    static half_t *ah, *h1h, *hh, *w1h, *w2h, *wph, *owh, *ch;
    static float *xb, *kb, *bp;
    if (!init) {
        cudaGetSymbolAddress((void**)&ah,  g_ah);
        cudaGetSymbolAddress((void**)&h1h, g_h1h);
        cudaGetSymbolAddress((void**)&hh,  g_hh);
        cudaGetSymbolAddress((void**)&w1h, g_w1h);
        cudaGetSymbolAddress((void**)&w2h, g_w2h);
        cudaGetSymbolAddress((void**)&wph, g_wph);
        cudaGetSymbolAddress((void**)&owh, g_owh);
        cudaGetSymbolAddress((void**)&ch,  g_ch);
        cudaGetSymbolAddress((void**)&xb,  g_x);
        cudaGetSymbolAddress((void**)&kb,  g_k);
        cudaGetSymbolAddress((void**)&bp,  g_bproj);
        cudaFuncSetAttribute(mma_gemm<0>, cudaFuncAttributeMaxDynamicSharedMemorySize, GSMEM);
        cudaFuncSetAttribute(mma_gemm<1>, cudaFuncAttributeMaxDynamicSharedMemorySize, GSMEM);
        cudaFuncSetAttribute(mma_gemm<2>, cudaFuncAttributeMaxDynamicSharedMemorySize, GSMEM);
        init = true;
    }

    // Launch order chosen so GEMM1 sits at the ncu capture window (3rd launch).
    // 0: gather+round A
    gsplit_k<<<TOK * 64 / 256, 256>>>(seq, embed, ah);
    // 1: w1 transpose
    tsplit1_k<<<dim3(FF / 32, HID / 32), 256>>>(w1, HID, FF, w1h);
    // 2: GEMM1: relu(e @ w1 + b1) -> h1 (fp16)      [65536 x 1024, K=512]
    mma_gemm<0><<<dim3(FF / 128, TOK / 128), 256, GSMEM>>>(
        TOK, FF, HID, ah, w1h, b1, nullptr, h1h, nullptr, nullptr);
    // 3: w2 transpose
    tsplit1_k<<<dim3(HID / 32, FF / 32), 256>>>(w2, FF, HID, w2h);
    // 4: GEMM2: x = h1 @ w2 + b2 + e -> fp32        [65536 x 512, K=1024]
    mma_gemm<1><<<dim3(HID / 128, TOK / 128), 256, GSMEM>>>(
        TOK, HID, FF, h1h, w2h, b2, xb, nullptr, seq, embed);
    // 5: LayerNorm -> h (fp16)
    ln_split_k<<<TOK / 8, 256>>>(xb, lng, lnb, hh);
    // 6,7: sem/epi weight transposes
    tsplit1_k<<<dim3(HALF_ / 32, HID / 32), 256>>>(sw, HID, HALF_, wph);
    tsplit1_k<<<dim3(HALF_ / 32, HID / 32), 256>>>(ew, HID, HALF_, wph + (size_t)HALF_ * HID);
    // 8: bias pack
    bpack_k<<<2, 256>>>(sb, eb);
    // 9: GEMM3: k = h @ [sem|epi] + bias -> fp32    [65536 x 512, K=512]
    mma_gemm<2><<<dim3(HID / 128, TOK / 128), 256, GSMEM>>>(
        TOK, HID, HID, hh, wph, bp, kb, nullptr, nullptr, nullptr);
    // 10: backward scan -> c (fp16)
    scan_k<<<128, 32>>>(kb, ch);
    // 11: out_w transpose
    tsplit1_k<<<dim3(VOC / 32, HID / 32), 256>>>(ow, HID, VOC, owh);
    // 12: GEMM4: out = c @ out_w + out_b            [64 x 32000, K=512]
    mma_gemm<2><<<dim3(VOC / 128, 1), 256, GSMEM>>>(
        BATCH, VOC, HID, ch, owh, ob, out, nullptr, nullptr, nullptr);
}

// round 17
// speedup vs baseline: 1.0019x; 1.0019x over previous
#include <cuda_runtime.h>
#include <cuda_fp16.h>
#include <cstdint>

// Problem constants
#define TOK   65536      // B*L
#define BATCH 64
#define SEQL  1024
#define HID   512
#define FF    1024
#define HALF_ 256
#define VOC   32000

typedef __half half_t;

__device__ __forceinline__ uint32_t smem_u32(const void* p) {
    uint32_t a;
    asm("{ .reg .u64 t; cvta.to.shared.u64 t, %1; cvt.u32.u64 %0, t; }" : "=r"(a) : "l"(p));
    return a;
}
#define SW128(o) ((o) ^ (((o) >> 3) & 0x70))

__device__ __forceinline__ void ldsm4(uint32_t* r, uint32_t a) {
    asm volatile("ldmatrix.sync.aligned.m8n8.x4.shared.b16 {%0,%1,%2,%3}, [%4];"
        : "=r"(r[0]), "=r"(r[1]), "=r"(r[2]), "=r"(r[3]) : "r"(a));
}
__device__ __forceinline__ void mma16816(float* c, const uint32_t* a, const uint32_t* b) {
    asm volatile("mma.sync.aligned.m16n8k16.row.col.f32.f16.f16.f32 "
        "{%0,%1,%2,%3}, {%4,%5,%6,%7}, {%8,%9}, {%0,%1,%2,%3};"
        : "+f"(c[0]), "+f"(c[1]), "+f"(c[2]), "+f"(c[3])
        : "r"(a[0]), "r"(a[1]), "r"(a[2]), "r"(a[3]), "r"(b[0]), "r"(b[1]));
}
__device__ __forceinline__ void cp16(uint32_t dst, const void* src, bool pred) {
    const int sz = pred ? 16 : 0;
    asm volatile("cp.async.cg.shared.global [%0], [%1], 16, %2;"
        :: "r"(dst), "l"(src), "r"(sz) : "memory");
}
#define CP_COMMIT() asm volatile("cp.async.commit_group;" ::: "memory")
template<int N>
__device__ __forceinline__ void cp_wait() {
    asm volatile("cp.async.wait_group %0;" :: "n"(N) : "memory");
}

// -------- scratch (device globals) --------
__device__ half_t g_ah[(size_t)TOK * HID];
__device__ half_t g_h1h[(size_t)TOK * FF];
__device__ half_t g_hh[(size_t)TOK * HID];
__device__ float  g_x[(size_t)TOK * HID];
__device__ float  g_k[(size_t)TOK * HID];
__device__ half_t g_w1h[(size_t)FF * HID];
__device__ half_t g_w2h[(size_t)HID * FF];
__device__ half_t g_wph[(size_t)HID * HID];
__device__ half_t g_owh[(size_t)VOC * HID];
__device__ float  g_bproj[HID];
__device__ half_t g_ch[BATCH * HID];

// ============================================================
// mma.sync fp16 single-pass GEMM, cp.async 3-stage pipeline, BK=64.
// BM = 128 (256 thr, 8 warps) or 64 (128 thr, 4 warps); warp tile 32x64.
// C[M,N] = A[M,K] @ B^T;  A [M,K] K-major fp16, B [N,K] K-major fp16.
// smem: 128B row = 64 contiguous fp16 k-elems, SW128.
// Stage = BM*128 (A) + 16KB (B); 3 stages; one sync per chunk.
// EPI: 0 = relu(acc+bias) -> fp16; 1 = acc+bias+embed[seq[m]] -> f32;
//      2 = acc+bias -> f32.
// ============================================================
#define NSTAGE 3

template<int EPI, int BM>
__global__ void __launch_bounds__(BM == 128 ? 256 : 128, 2) mma_gemm(
    int Mrows, int N, int K,
    const half_t* __restrict__ Ah, const half_t* __restrict__ Bh,
    const float* __restrict__ bias,
    float* __restrict__ Cf, half_t* __restrict__ Chi,
    const int* __restrict__ seq, const float* __restrict__ embed)
{
    constexpr int ASTG = BM * 128;
    constexpr int GST  = ASTG + 16384;
    extern __shared__ __align__(1024) char smem[];
    const uint32_t sbase = smem_u32(smem);
    const int tid = threadIdx.x;
    const int bm = blockIdx.y * BM;
    const int bn = blockIdx.x * 128;
    const int wid = tid >> 5, lane = tid & 31;
    int wm, wn;
    if (BM == 128) { wm = (wid & 3) * 32; wn = (wid >> 2) * 64; }
    else           { wm = (wid & 1) * 32; wn = (wid >> 1) * 64; }
    const bool mguard = (Mrows & (BM - 1)) != 0;

    // loader mapping
    const int a_lrow = tid >> 1;                 // A: 2 thr per row
    const int lw4 = (tid & 1) * 4;
    const int b_lrow = (BM == 128) ? (tid >> 1) : tid;   // B: 128 rows
    const int am = bm + a_lrow;
    const bool av = !mguard || (am < Mrows);
    const size_t aoff = (size_t)(av ? am : 0) * K;
    const size_t boff = (size_t)(bn + b_lrow) * K;

    // A ldmatrix lane addressing (m16 x k16 per x4)
    const int a_mi = lane >> 3;
    const int a_row = (lane & 7) + (a_mi & 1) * 8;
    const int a_kb = (a_mi >> 1) * 16;
    // B ldmatrix lane addressing (2 n8 tiles x 2 k8-halves per x4)
    const int b_g = lane >> 3;
    const int b_row = lane & 7;
    const int b_nt = b_g >> 1;
    const int b_kh = (b_g & 1) * 16;

    float c[16][4];                     // [mt*8 + nt][4], mt<2, nt<8
#pragma unroll
    for (int i = 0; i < 16; i++)
#pragma unroll
        for (int j = 0; j < 4; j++) c[i][j] = 0.f;

    const int NCH = K >> 6;             // BK = 64

    auto load_stage = [&](int s, int k0) {
        const uint32_t sA = sbase + s * GST;
        const uint32_t sB = sA + ASTG;
        if (BM == 128) {
#pragma unroll
            for (int it = 0; it < 4; it++) {
                const int word = lw4 + it;             // 0..7
                const uint32_t so = SW128((uint32_t)(a_lrow * 128 + word * 16));
                const size_t ko = (size_t)(k0 + word * 8);
                cp16(sA + so, Ah + aoff + ko, av);
                cp16(sB + so, Bh + boff + ko, true);
            }
        } else {
#pragma unroll
            for (int it = 0; it < 4; it++) {
                const int word = lw4 + it;
                const uint32_t so = SW128((uint32_t)(a_lrow * 128 + word * 16));
                cp16(sA + so, Ah + aoff + (size_t)(k0 + word * 8), av);
            }
#pragma unroll
            for (int it = 0; it < 8; it++) {
                const uint32_t so = SW128((uint32_t)(b_lrow * 128 + it * 16));
                cp16(sB + so, Bh + boff + (size_t)(k0 + it * 8), true);
            }
        }
    };

    load_stage(0, 0);
    CP_COMMIT();
    load_stage(1, 64);
    CP_COMMIT();

    int stage = 0;
    for (int ch = 0; ch < NCH; ch++) {
        if (ch + 1 < NCH) cp_wait<1>(); else cp_wait<0>();
        __syncthreads();
        if (ch + 2 < NCH) {
            int ns = stage + 2; if (ns >= NSTAGE) ns -= NSTAGE;
            load_stage(ns, (ch + 2) * 64);
        }
        CP_COMMIT();   // always commit (possibly empty) to keep accounting
        const uint32_t sAu = sbase + stage * GST;
        const uint32_t sBu = sAu + ASTG;
        // ---- compute: 4 k16 steps ----
#pragma unroll
        for (int k16 = 0; k16 < 4; k16++) {
            const int kb = k16 * 32;
            uint32_t bfrag[4][4];       // 8 n8 tiles (64 cols)
#pragma unroll
            for (int p = 0; p < 4; p++) {
                const int n = wn + (p * 2 + b_nt) * 8 + b_row;
                ldsm4(bfrag[p], sBu + SW128((uint32_t)(n * 128) + kb + b_kh));
            }
            uint32_t a[2][4];
#pragma unroll
            for (int mt = 0; mt < 2; mt++)
                ldsm4(a[mt], sAu + SW128((uint32_t)((wm + mt * 16 + a_row) * 128) + kb + a_kb));
#pragma unroll
            for (int mt = 0; mt < 2; mt++)
#pragma unroll
                for (int nt = 0; nt < 8; nt++)
                    mma16816(c[mt * 8 + nt], a[mt], &bfrag[nt >> 1][(nt & 1) * 2]);
        }
        if (++stage >= NSTAGE) stage = 0;
    }

    // ---- epilogue ----
    const int mrow = lane >> 2;
    const int mcol = (lane & 3) * 2;
#pragma unroll
    for (int mt = 0; mt < 2; mt++) {
        const int r0 = bm + wm + mt * 16 + mrow;
        const int r1 = r0 + 8;
        const bool v0 = !mguard || (r0 < Mrows);
        const bool v1 = !mguard || (r1 < Mrows);
        const float* e0 = nullptr;
        const float* e1 = nullptr;
        if (EPI == 1) {
            if (v0) e0 = embed + (size_t)seq[r0] * HID;
            if (v1) e1 = embed + (size_t)seq[r1] * HID;
        }
#pragma unroll
        for (int nt = 0; nt < 8; nt++) {
            const int col = bn + wn + nt * 8 + mcol;
            float* cc = c[mt * 8 + nt];
            const float b0v = bias[col], b1v = bias[col + 1];
            float x0 = cc[0] + b0v, x1 = cc[1] + b1v;
            float x2 = cc[2] + b0v, x3 = cc[3] + b1v;
            if (EPI == 0) {
                x0 = fmaxf(x0, 0.f); x1 = fmaxf(x1, 0.f);
                x2 = fmaxf(x2, 0.f); x3 = fmaxf(x3, 0.f);
                if (v0) {
                    __half2 ph; ph.x = __float2half_rn(x0); ph.y = __float2half_rn(x1);
                    *(__half2*)(Chi + (size_t)r0 * N + col) = ph;
                }
                if (v1) {
                    __half2 ph; ph.x = __float2half_rn(x2); ph.y = __float2half_rn(x3);
                    *(__half2*)(Chi + (size_t)r1 * N + col) = ph;
                }
            } else {
                if (EPI == 1) {
                    if (v0) { x0 += e0[col]; x1 += e0[col + 1]; }
                    if (v1) { x2 += e1[col]; x3 += e1[col + 1]; }
                }
                if (v0) *(float2*)(Cf + (size_t)r0 * N + col) = make_float2(x0, x1);
                if (v1) *(float2*)(Cf + (size_t)r1 * N + col) = make_float2(x2, x3);
            }
        }
    }
}

#define GSMEM128 (NSTAGE * (128 * 128 + 16384))
#define GSMEM64  (NSTAGE * (64 * 128 + 16384))

// ============================================================
// gather + round:  Ahi[m] = fp16(embed[seq[m]])
// ============================================================
__global__ void __launch_bounds__(256) gsplit_k(const int* __restrict__ seq,
                                                const float* __restrict__ embed,
                                                half_t* __restrict__ hi)
{
    const size_t idx = (size_t)blockIdx.x * 256 + threadIdx.x;   // TOK*64
    const int t = (int)(idx >> 6), c = (int)(idx & 63) * 8;
    const float* p = embed + (size_t)seq[t] * HID + c;
    float4 a = *(const float4*)p;
    float4 b = *(const float4*)(p + 4);
    float vv[8] = {a.x, a.y, a.z, a.w, b.x, b.y, b.z, b.w};
    const size_t ob = (size_t)t * HID + c;
#pragma unroll
    for (int j = 0; j < 8; j += 2) {
        __half2 ph; ph.x = __float2half_rn(vv[j]); ph.y = __float2half_rn(vv[j + 1]);
        *(__half2*)(hi + ob + j) = ph;
    }
}

// ============================================================
// Tiled transpose + round: W[K,N] fp32 -> out[N,K] single fp16.
// ============================================================
__global__ void __launch_bounds__(256) tsplit1_k(const float* __restrict__ W, int K, int N,
                                                 half_t* __restrict__ ht)
{
    __shared__ float t[32][33];
    const int tx = threadIdx.x & 31, ty = threadIdx.x >> 5;
    const int n0 = blockIdx.x * 32, k0 = blockIdx.y * 32;
#pragma unroll
    for (int i = 0; i < 4; i++)
        t[ty + 8 * i][tx] = W[(size_t)(k0 + ty + 8 * i) * N + n0 + tx];
    __syncthreads();
#pragma unroll
    for (int i = 0; i < 4; i++) {
        const size_t o = (size_t)(n0 + ty + 8 * i) * K + k0 + tx;
        ht[o] = __float2half_rn(t[tx][ty + 8 * i]);
    }
}

// ============================================================
// LayerNorm (warp per row) -> fp16 output.
// ============================================================
__global__ void __launch_bounds__(256) ln_split_k(const float* __restrict__ x,
                                                  const float* __restrict__ g,
                                                  const float* __restrict__ b,
                                                  half_t* __restrict__ hh)
{
    const int row = blockIdx.x * 8 + (threadIdx.x >> 5);
    const int ln = threadIdx.x & 31;
    const float* xr = x + (size_t)row * HID + ln * 16;
    float v[16];
    *(float4*)&v[0]  = ((const float4*)xr)[0];
    *(float4*)&v[4]  = ((const float4*)xr)[1];
    *(float4*)&v[8]  = ((const float4*)xr)[2];
    *(float4*)&v[12] = ((const float4*)xr)[3];
    float s = 0.f;
#pragma unroll
    for (int j = 0; j < 16; j++) s += v[j];
#pragma unroll
    for (int o = 16; o; o >>= 1) s += __shfl_xor_sync(0xffffffffu, s, o);
    const float mean = s * (1.f / 512.f);
    float q = 0.f;
#pragma unroll
    for (int j = 0; j < 16; j++) { float d = v[j] - mean; q += d * d; }
#pragma unroll
    for (int o = 16; o; o >>= 1) q += __shfl_xor_sync(0xffffffffu, q, o);
    const float r = rsqrtf(q * (1.f / 512.f) + 1e-5f);
    const size_t ob = (size_t)row * HID + ln * 16;
#pragma unroll
    for (int j = 0; j < 16; j += 2) {
        const int c0 = ln * 16 + j;
        float y0 = (v[j] - mean) * r * g[c0] + b[c0];
        float y1 = (v[j + 1] - mean) * r * g[c0 + 1] + b[c0 + 1];
        __half2 ph; ph.x = __float2half_rn(y0); ph.y = __float2half_rn(y1);
        *(__half2*)(hh + ob + j) = ph;
    }
}

// ============================================================
__global__ void bpack_k(const float* __restrict__ sb, const float* __restrict__ eb)
{
    const int i = blockIdx.x * 256 + threadIdx.x;
    if (i < HID) g_bproj[i] = (i < HALF_) ? sb[i] : eb[i - HALF_];
}

// ============================================================
// Backward vector scan, 2 steps per iteration, inline norms,
// depth-2 row prefetch, fp16 output (c for GEMM4).
// ============================================================
__global__ void __launch_bounds__(32) scan_k(const float* __restrict__ kall,
                                             half_t* __restrict__ chh)
{
    const int chain = blockIdx.x;
    const int b = chain >> 1, wh = chain & 1;
    const int ln = threadIdx.x;
    const float* base = kall + (size_t)b * SEQL * HID + wh * HALF_ + ln * 8;

#define LOADROW(dst, t) do { \
    float4 _a = *(const float4*)(base + (size_t)(t) * HID); \
    float4 _b = *(const float4*)(base + (size_t)(t) * HID + 4); \
    dst[0]=_a.x; dst[1]=_a.y; dst[2]=_a.z; dst[3]=_a.w; \
    dst[4]=_b.x; dst[5]=_b.y; dst[6]=_b.z; dst[7]=_b.w; } while (0)

    float u[8], acc[8], k0[8], k1[8], p0[8], p1[8];
    LOADROW(u, SEQL - 1);
#pragma unroll
    for (int j = 0; j < 8; j++) acc[j] = 0.f;

    // ---- single first step t = 1022 ----
    {
        float kc[8];
        LOADROW(kc, SEQL - 2);
        LOADROW(k0, SEQL - 3);   // t=1021
        LOADROW(k1, SEQL - 4);   // t=1020
        LOADROW(p0, SEQL - 5);   // t=1019
        LOADROW(p1, SEQL - 6);   // t=1018
        float pa = 0.f, n0 = 0.f;
#pragma unroll
        for (int j = 0; j < 8; j++) { pa += kc[j] * u[j]; n0 += kc[j] * kc[j]; }
#pragma unroll
        for (int o = 16; o; o >>= 1) {
            pa += __shfl_xor_sync(0xffffffffu, pa, o);
            n0 += __shfl_xor_sync(0xffffffffu, n0, o);
        }
        const float w = wh ? (1023.f / 1024.f) : 1.f;
        const float ws = w * pa;
        const float us = ws / (n0 + 1e-6f);
#pragma unroll
        for (int j = 0; j < 8; j++) { acc[j] += ws * kc[j]; u[j] -= us * kc[j]; }
    }

    // ---- pair loop: t = 1021, 1019, ..., 1 (511 iterations) ----
    for (int t = SEQL - 3; t >= 1; t -= 2) {
        float q0[8] = {0, 0, 0, 0, 0, 0, 0, 0};
        float q1[8] = {0, 0, 0, 0, 0, 0, 0, 0};
        if (t >= 5) {
            LOADROW(q0, t - 4);
            LOADROW(q1, t - 5);
        }
        float pa = 0.f, pb = 0.f, pg = 0.f, n0 = 0.f, n1 = 0.f;
#pragma unroll
        for (int j = 0; j < 8; j++) {
            pa += k0[j] * u[j];
            pb += k1[j] * u[j];
            pg += k1[j] * k0[j];
            n0 += k0[j] * k0[j];
            n1 += k1[j] * k1[j];
        }
#pragma unroll
        for (int o = 16; o; o >>= 1) {
            pa += __shfl_xor_sync(0xffffffffu, pa, o);
            pb += __shfl_xor_sync(0xffffffffu, pb, o);
            pg += __shfl_xor_sync(0xffffffffu, pg, o);
            n0 += __shfl_xor_sync(0xffffffffu, n0, o);
            n1 += __shfl_xor_sync(0xffffffffu, n1, o);
        }
        const float inv1024 = 1.f / 1024.f;
        const float w0 = wh ? (float)(t + 1) * inv1024 : 1.f;
        const float w1 = wh ? (float)t * inv1024 : 1.f;
        const float id0 = 1.f / (n0 + 1e-6f);
        const float id1 = 1.f / (n1 + 1e-6f);
        const float ws0 = w0 * pa;
        const float us0 = ws0 * id0;
        const float s1 = pb - us0 * pg;
        const float ws1 = w1 * s1;
        const float us1 = ws1 * id1;
#pragma unroll
        for (int j = 0; j < 8; j++) {
            acc[j] += ws0 * k0[j] + ws1 * k1[j];
            u[j]   -= us0 * k0[j] + us1 * k1[j];
        }
#pragma unroll
        for (int j = 0; j < 8; j++) {
            k0[j] = p0[j]; k1[j] = p1[j];
            p0[j] = q0[j]; p1[j] = q1[j];
        }
    }

    const size_t ob = (size_t)b * HID + wh * HALF_ + ln * 8;
#pragma unroll
    for (int j = 0; j < 8; j += 2) {
        __half2 ph;
        ph.x = __float2half_rn(acc[j]);
        ph.y = __float2half_rn(acc[j + 1]);
        *(__half2*)(chh + ob + j) = ph;
    }
#undef LOADROW
}

// ============================================================
extern "C" void kernel_launch(void* const* d_in, const int* in_sizes, int n_in,
                              void* d_out, int out_size)
{
    const int*   seq   = (const int*)d_in[0];
    const float* embed = (const float*)d_in[1];
    const float* w1    = (const float*)d_in[2];
    const float* b1    = (const float*)d_in[3];
    const float* w2    = (const float*)d_in[4];
    const float* b2    = (const float*)d_in[5];
    const float* lng   = (const float*)d_in[6];
    const float* lnb   = (const float*)d_in[7];
    const float* sw    = (const float*)d_in[8];
    const float* sb    = (const float*)d_in[9];
    const float* ew    = (const float*)d_in[10];
    const float* eb    = (const float*)d_in[11];
    const float* ow    = (const float*)d_in[12];
    const float* ob    = (const float*)d_in[13];
    float* out = (float*)d_out;

    static bool init = false;
    static half_t *ah, *h1h, *hh, *w1h, *w2h, *wph, *owh, *ch;
    static float *xb, *kb, *bp;
    static cudaStream_t s1;
    static cudaEvent_t e_fork, e_w1, e_w2, e_pre;
    if (!init) {
        cudaGetSymbolAddress((void**)&ah,  g_ah);
        cudaGetSymbolAddress((void**)&h1h, g_h1h);
        cudaGetSymbolAddress((void**)&hh,  g_hh);
        cudaGetSymbolAddress((void**)&w1h, g_w1h);
        cudaGetSymbolAddress((void**)&w2h, g_w2h);
        cudaGetSymbolAddress((void**)&wph, g_wph);
        cudaGetSymbolAddress((void**)&owh, g_owh);
        cudaGetSymbolAddress((void**)&ch,  g_ch);
        cudaGetSymbolAddress((void**)&xb,  g_x);
        cudaGetSymbolAddress((void**)&kb,  g_k);
        cudaGetSymbolAddress((void**)&bp,  g_bproj);
        cudaFuncSetAttribute(mma_gemm<0, 128>, cudaFuncAttributeMaxDynamicSharedMemorySize, GSMEM128);
        cudaFuncSetAttribute(mma_gemm<1, 128>, cudaFuncAttributeMaxDynamicSharedMemorySize, GSMEM128);
        cudaFuncSetAttribute(mma_gemm<2, 128>, cudaFuncAttributeMaxDynamicSharedMemorySize, GSMEM128);
        cudaFuncSetAttribute(mma_gemm<2, 64>,  cudaFuncAttributeMaxDynamicSharedMemorySize, GSMEM64);
        cudaStreamCreateWithFlags(&s1, cudaStreamNonBlocking);
        cudaEventCreateWithFlags(&e_fork, cudaEventDisableTiming);
        cudaEventCreateWithFlags(&e_w1,   cudaEventDisableTiming);
        cudaEventCreateWithFlags(&e_w2,   cudaEventDisableTiming);
        cudaEventCreateWithFlags(&e_pre,  cudaEventDisableTiming);
        init = true;
    }

    // ---- fork side stream for weight preprocessing ----
    cudaEventRecord(e_fork, 0);
    cudaStreamWaitEvent(s1, e_fork, 0);

    // side stream: weight transposes + bias pack
    tsplit1_k<<<dim3(FF / 32, HID / 32), 256, 0, s1>>>(w1, HID, FF, w1h);
    cudaEventRecord(e_w1, s1);
    tsplit1_k<<<dim3(HID / 32, FF / 32), 256, 0, s1>>>(w2, FF, HID, w2h);
    cudaEventRecord(e_w2, s1);
    tsplit1_k<<<dim3(HALF_ / 32, HID / 32), 256, 0, s1>>>(sw, HID, HALF_, wph);
    tsplit1_k<<<dim3(HALF_ / 32, HID / 32), 256, 0, s1>>>(ew, HID, HALF_, wph + (size_t)HALF_ * HID);
    bpack_k<<<2, 256, 0, s1>>>(sb, eb);
    tsplit1_k<<<dim3(VOC / 32, HID / 32), 256, 0, s1>>>(ow, HID, VOC, owh);
    cudaEventRecord(e_pre, s1);

    // main stream
    gsplit_k<<<TOK * 64 / 256, 256>>>(seq, embed, ah);

    cudaStreamWaitEvent(0, e_w1, 0);
    // GEMM1: relu(e @ w1 + b1) -> h1 (fp16)         [65536 x 1024, K=512]
    mma_gemm<0, 128><<<dim3(FF / 128, TOK / 128), 256, GSMEM128>>>(
        TOK, FF, HID, ah, w1h, b1, nullptr, h1h, nullptr, nullptr);

    cudaStreamWaitEvent(0, e_w2, 0);
    // GEMM2: x = h1 @ w2 + b2 + e -> fp32           [65536 x 512, K=1024]
    mma_gemm<1, 128><<<dim3(HID / 128, TOK / 128), 256, GSMEM128>>>(
        TOK, HID, FF, h1h, w2h, b2, xb, nullptr, seq, embed);

    // LayerNorm -> h (fp16)
    ln_split_k<<<TOK / 8, 256>>>(xb, lng, lnb, hh);

    cudaStreamWaitEvent(0, e_pre, 0);
    // GEMM3: k = h @ [sem|epi] + bias -> fp32       [65536 x 512, K=512]
    mma_gemm<2, 128><<<dim3(HID / 128, TOK / 128), 256, GSMEM128>>>(
        TOK, HID, HID, hh, wph, bp, kb, nullptr, nullptr, nullptr);

    // backward scan -> c (fp16)
    scan_k<<<128, 32>>>(kb, ch);

    // GEMM4 (thin-M 64-row tile): out = c @ out_w + out_b   [64 x 32000, K=512]
    mma_gemm<2, 64><<<dim3(VOC / 128, 1), 128, GSMEM64>>>(
        BATCH, VOC, HID, ch, owh, ob, out, nullptr, nullptr, nullptr);
}